// round 2
// baseline (speedup 1.0000x reference)
#include <cuda_runtime.h>
#include <cuda_bf16.h>
#include <math.h>

// Problem constants
#define TT 70
#define BB 128
#define EE 400
#define HH 1150
#define VV 33278

// ---------------------------------------------------------------------------
// Scratch (device globals; no runtime allocation allowed)
// ---------------------------------------------------------------------------
__device__ float g_emb  [TT * BB * EE];        // embedded inputs        [T,B,E]
__device__ float g_xproj[TT * BB * 4 * HH];    // per-layer x-projection [T,B,4*nh] (reused)
__device__ float g_x1   [TT * BB * HH];        // layer0 output / layer1 input
__device__ float g_x2   [TT * BB * HH];        // layer1 output / layer2 input
__device__ float g_x3   [TT * BB * EE];        // layer2 output / decoder input
__device__ float g_c    [2 * BB * HH];         // cell-state ping-pong (max width)

// ---------------------------------------------------------------------------
// Embedding gather: out[t,b,:] = emb[tokens[t,b],:]
// ---------------------------------------------------------------------------
__global__ void embed_kernel(const int* __restrict__ tokens,
                             const float* __restrict__ emb,
                             float* __restrict__ out)
{
    int tb = blockIdx.x;                       // 0 .. T*B-1
    int tok = tokens[tb];
    const float* src = emb + (size_t)tok * EE;
    float* dst = out + (size_t)tb * EE;
    for (int e = threadIdx.x; e < EE; e += blockDim.x)
        dst[e] = src[e];
}

// ---------------------------------------------------------------------------
// SGEMM (NT): C[m,n] = sum_k A[m,k] * B[n,k] + bias1[n] + bias2[n]
// A: [M,K] row-major,  B: [N,K] row-major.
// Tile 64x64, Ktile 16, 256 threads, 4x4 outputs/thread.
// ---------------------------------------------------------------------------
__global__ void sgemm_nt_bias(const float* __restrict__ A,
                              const float* __restrict__ B,
                              const float* __restrict__ bias1,
                              const float* __restrict__ bias2,
                              float* __restrict__ C,
                              int M, int N, int K)
{
    const int TM = 64, TN = 64, TK = 16;
    __shared__ float As[TK][TM];
    __shared__ float Bs[TK][TN];

    int tid = threadIdx.x;           // 0..255
    int tx  = tid & 15;              // 0..15 -> n
    int ty  = tid >> 4;              // 0..15 -> m
    int m0  = blockIdx.y * TM;
    int n0  = blockIdx.x * TN;

    float acc[4][4] = {};

    for (int k0 = 0; k0 < K; k0 += TK) {
        // Load A tile and B tile (coalesced along K)
        #pragma unroll
        for (int idx = tid; idx < TM * TK; idx += 256) {
            int k = idx & (TK - 1);
            int r = idx >> 4;             // row within tile
            int gk = k0 + k;
            int gm = m0 + r;
            As[k][r] = (gm < M && gk < K) ? A[(size_t)gm * K + gk] : 0.0f;
            int gn = n0 + r;
            Bs[k][r] = (gn < N && gk < K) ? B[(size_t)gn * K + gk] : 0.0f;
        }
        __syncthreads();

        #pragma unroll
        for (int k = 0; k < TK; k++) {
            float a[4], b[4];
            #pragma unroll
            for (int i = 0; i < 4; i++) a[i] = As[k][ty * 4 + i];
            #pragma unroll
            for (int j = 0; j < 4; j++) b[j] = Bs[k][tx * 4 + j];
            #pragma unroll
            for (int i = 0; i < 4; i++)
                #pragma unroll
                for (int j = 0; j < 4; j++)
                    acc[i][j] += a[i] * b[j];
        }
        __syncthreads();
    }

    #pragma unroll
    for (int i = 0; i < 4; i++) {
        int m = m0 + ty * 4 + i;
        if (m >= M) continue;
        #pragma unroll
        for (int j = 0; j < 4; j++) {
            int n = n0 + tx * 4 + j;
            if (n >= N) continue;
            float v = acc[i][j];
            if (bias1) v += bias1[n];
            if (bias2) v += bias2[n];
            C[(size_t)m * N + n] = v;
        }
    }
}

// ---------------------------------------------------------------------------
// Fused LSTM step:
//   gates[b, g*nh + j] = xp[b, g*nh + j] + sum_k h_in[b,k] * W[g*nh + j, k]
//   i,f,o = sigmoid; g = tanh;  c_out = f*c_in + i*g;  h = o*tanh(c_out)
//   h written to y_out (doubles as next step's h_in), c to c_out.
// Tile: 32 (batch) x 32 (j), 256 threads, each thread 2x2 outputs x 4 gates.
// ---------------------------------------------------------------------------
__global__ void lstm_step(const float* __restrict__ h_in,   // [B, nh]
                          const float* __restrict__ c_in,   // [B, nh]
                          const float* __restrict__ W,      // [4*nh, nh]
                          const float* __restrict__ xp,     // [B, 4*nh]
                          float* __restrict__ c_out,        // [B, nh]
                          float* __restrict__ y_out,        // [B, nh]
                          int nh)
{
    const int TM = 32, TN = 32, KT = 16;
    __shared__ float Hs[KT][TM];
    __shared__ float Ws[4][KT][TN];

    int tid = threadIdx.x;           // 0..255
    int tx  = tid & 15;
    int ty  = tid >> 4;
    int m0  = blockIdx.y * TM;       // batch offset
    int n0  = blockIdx.x * TN;       // j offset

    float acc[4][2][2] = {};

    for (int k0 = 0; k0 < nh; k0 += KT) {
        // Hs: 32x16 = 512 elems
        #pragma unroll
        for (int idx = tid; idx < TM * KT; idx += 256) {
            int k = idx & (KT - 1);
            int m = idx >> 4;
            int gk = k0 + k;
            Hs[k][m] = (gk < nh) ? h_in[(size_t)(m0 + m) * nh + gk] : 0.0f;
        }
        // Ws: 4x32x16 = 2048 elems
        #pragma unroll
        for (int idx = tid; idx < 4 * TN * KT; idx += 256) {
            int k = idx & (KT - 1);
            int n = (idx >> 4) & (TN - 1);
            int g = idx >> 9;
            int gn = n0 + n;
            int gk = k0 + k;
            Ws[g][k][n] = (gn < nh && gk < nh)
                        ? W[(size_t)(g * nh + gn) * nh + gk] : 0.0f;
        }
        __syncthreads();

        #pragma unroll
        for (int k = 0; k < KT; k++) {
            float a0 = Hs[k][ty * 2];
            float a1 = Hs[k][ty * 2 + 1];
            #pragma unroll
            for (int g = 0; g < 4; g++) {
                float b0 = Ws[g][k][tx * 2];
                float b1 = Ws[g][k][tx * 2 + 1];
                acc[g][0][0] += a0 * b0;
                acc[g][0][1] += a0 * b1;
                acc[g][1][0] += a1 * b0;
                acc[g][1][1] += a1 * b1;
            }
        }
        __syncthreads();
    }

    // pointwise LSTM
    #pragma unroll
    for (int i = 0; i < 2; i++) {
        int b = m0 + ty * 2 + i;
        const float* xpb = xp + (size_t)b * 4 * nh;
        #pragma unroll
        for (int j = 0; j < 2; j++) {
            int n = n0 + tx * 2 + j;
            if (n >= nh) continue;
            float gi = acc[0][i][j] + xpb[n];
            float gf = acc[1][i][j] + xpb[nh + n];
            float gg = acc[2][i][j] + xpb[2 * nh + n];
            float go = acc[3][i][j] + xpb[3 * nh + n];
            float iv = 1.0f / (1.0f + expf(-gi));
            float fv = 1.0f / (1.0f + expf(-gf));
            float gv = tanhf(gg);
            float ov = 1.0f / (1.0f + expf(-go));
            float cv = fv * c_in[(size_t)b * nh + n] + iv * gv;
            float hv = ov * tanhf(cv);
            c_out[(size_t)b * nh + n] = cv;
            y_out[(size_t)b * nh + n] = hv;
        }
    }
}

// ---------------------------------------------------------------------------
// Host-side layer driver
// ---------------------------------------------------------------------------
static void run_layer(const float* x_in, int in_dim, int nh,
                      const float* W_ih, const float* W_hh,
                      const float* b_ih, const float* b_hh,
                      const float* h0, const float* c0,
                      float* x_out, float* xproj, float* cbuf)
{
    // Input projection for all timesteps: xproj = x_in @ W_ih^T + b_ih + b_hh
    {
        dim3 grid((4 * nh + 63) / 64, (TT * BB + 63) / 64);
        sgemm_nt_bias<<<grid, 256>>>(x_in, W_ih, b_ih, b_hh, xproj,
                                     TT * BB, 4 * nh, in_dim);
    }
    // Sequential recurrence
    dim3 gstep((nh + 31) / 32, BB / 32);
    for (int t = 0; t < TT; t++) {
        const float* h_in = (t == 0) ? h0 : x_out + (size_t)(t - 1) * BB * nh;
        const float* c_in = (t == 0) ? c0 : cbuf + (size_t)((t - 1) & 1) * BB * HH;
        float* c_out = cbuf + (size_t)(t & 1) * BB * HH;
        float* y_out = x_out + (size_t)t * BB * nh;
        const float* xp = xproj + (size_t)t * BB * 4 * nh;
        lstm_step<<<gstep, 256>>>(h_in, c_in, W_hh, xp, c_out, y_out, nh);
    }
}

extern "C" void kernel_launch(void* const* d_in, const int* in_sizes, int n_in,
                              void* d_out, int out_size)
{
    const int*   tokens = (const int*)  d_in[0];
    const float* h0_0   = (const float*)d_in[1];
    const float* c0_0   = (const float*)d_in[2];
    const float* h0_1   = (const float*)d_in[3];
    const float* c0_1   = (const float*)d_in[4];
    const float* h0_2   = (const float*)d_in[5];
    const float* c0_2   = (const float*)d_in[6];
    const float* embw   = (const float*)d_in[7];
    const float* W_ih0  = (const float*)d_in[8];
    const float* W_hh0  = (const float*)d_in[9];
    const float* b_ih0  = (const float*)d_in[10];
    const float* b_hh0  = (const float*)d_in[11];
    const float* W_ih1  = (const float*)d_in[12];
    const float* W_hh1  = (const float*)d_in[13];
    const float* b_ih1  = (const float*)d_in[14];
    const float* b_hh1  = (const float*)d_in[15];
    const float* W_ih2  = (const float*)d_in[16];
    const float* W_hh2  = (const float*)d_in[17];
    const float* b_ih2  = (const float*)d_in[18];
    const float* b_hh2  = (const float*)d_in[19];
    const float* dec_b  = (const float*)d_in[20];
    float* logits = (float*)d_out;

    float *emb_buf, *xproj, *x1, *x2, *x3, *cbuf;
    cudaGetSymbolAddress((void**)&emb_buf, g_emb);
    cudaGetSymbolAddress((void**)&xproj,   g_xproj);
    cudaGetSymbolAddress((void**)&x1,      g_x1);
    cudaGetSymbolAddress((void**)&x2,      g_x2);
    cudaGetSymbolAddress((void**)&x3,      g_x3);
    cudaGetSymbolAddress((void**)&cbuf,    g_c);

    // 1) Embedding
    embed_kernel<<<TT * BB, 128>>>(tokens, embw, emb_buf);

    // 2) Three LSTM layers
    run_layer(emb_buf, EE, HH, W_ih0, W_hh0, b_ih0, b_hh0, h0_0, c0_0, x1, xproj, cbuf);
    run_layer(x1,      HH, HH, W_ih1, W_hh1, b_ih1, b_hh1, h0_1, c0_1, x2, xproj, cbuf);
    run_layer(x2,      HH, EE, W_ih2, W_hh2, b_ih2, b_hh2, h0_2, c0_2, x3, xproj, cbuf);

    // 3) Tied decoder: logits = x3 @ embw^T + dec_b
    {
        dim3 grid((VV + 63) / 64, (TT * BB + 63) / 64);
        sgemm_nt_bias<<<grid, 256>>>(x3, embw, dec_b, (const float*)0,
                                     logits, TT * BB, VV, EE);
    }
}

// round 3
// speedup vs baseline: 3.6362x; 3.6362x over previous
#include <cuda_runtime.h>
#include <math.h>

// Problem constants
#define TT 70
#define BB 128
#define EE 400
#define HH 1150
#define VV 33278

// ---------------------------------------------------------------------------
// Scratch (device globals; no runtime allocation allowed)
// ---------------------------------------------------------------------------
__device__ float g_emb  [TT * BB * EE];         // embedded inputs [T,B,E]
__device__ float g_xproj[TT * BB * 4 * HH];     // x-projection, gate-reordered [T,B,4nh]
__device__ float g_x1   [TT * BB * HH];
__device__ float g_x2   [TT * BB * HH];
__device__ float g_x3   [TT * BB * EE];
__device__ float g_c    [2 * BB * HH];          // cell-state ping-pong
__device__ float g_Wih_r[4 * HH * HH];          // reordered W_ih (max 4600x1150)
__device__ float g_Whh_r[4 * HH * HH];          // reordered W_hh
__device__ float g_bias_r[4 * HH];              // reordered b_ih + b_hh

// ---------------------------------------------------------------------------
// Helpers: tf32 convert + mma
// ---------------------------------------------------------------------------
__device__ __forceinline__ unsigned f2tf(float f) {
    unsigned u;
    asm("cvt.rna.tf32.f32 %0, %1;" : "=r"(u) : "f"(f));
    return u;
}

__device__ __forceinline__ void mma_tf32(float c[4],
                                         unsigned a0, unsigned a1, unsigned a2, unsigned a3,
                                         unsigned b0, unsigned b1)
{
    asm("mma.sync.aligned.m16n8k8.row.col.f32.tf32.tf32.f32 "
        "{%0,%1,%2,%3},{%4,%5,%6,%7},{%8,%9},{%0,%1,%2,%3};"
        : "+f"(c[0]), "+f"(c[1]), "+f"(c[2]), "+f"(c[3])
        : "r"(a0), "r"(a1), "r"(a2), "r"(a3), "r"(b0), "r"(b1));
}

// ---------------------------------------------------------------------------
// Embedding gather
// ---------------------------------------------------------------------------
__global__ void embed_kernel(const int* __restrict__ tokens,
                             const float* __restrict__ emb,
                             float* __restrict__ out)
{
    int tb = blockIdx.x;
    int tok = tokens[tb];
    const float* src = emb + (size_t)tok * EE;
    float* dst = out + (size_t)tb * EE;
    for (int e = threadIdx.x; e < EE; e += blockDim.x)
        dst[e] = src[e];
}

// ---------------------------------------------------------------------------
// Weight preprocessing: reorder rows to gate-interleaved (r = j*4 + g)
// ---------------------------------------------------------------------------
__global__ void reorder_rows(const float* __restrict__ W, float* __restrict__ Wr,
                             int nh, int K)
{
    int row = blockIdx.x;                 // reordered row index, 0..4nh-1
    int j = row >> 2, g = row & 3;
    const float* src = W + (size_t)(g * nh + j) * K;
    float* dst = Wr + (size_t)row * K;
    for (int k = threadIdx.x; k < K; k += blockDim.x)
        dst[k] = src[k];
}

__global__ void combine_bias(const float* __restrict__ b1, const float* __restrict__ b2,
                             float* __restrict__ br, int nh)
{
    int r = blockIdx.x * blockDim.x + threadIdx.x;
    if (r < 4 * nh) {
        int j = r >> 2, g = r & 3;
        br[r] = b1[g * nh + j] + b2[g * nh + j];
    }
}

// ---------------------------------------------------------------------------
// TF32 GEMM (NT): C[m,n] = sum_k A[m,k]*B[n,k] (+ bias[n])
// Block 128x128, BK=32, 256 threads (8 warps, 2x4), warp tile 64x32.
// ---------------------------------------------------------------------------
__global__ void gemm_tf32(const float* __restrict__ A, const float* __restrict__ B,
                          const float* __restrict__ bias, float* __restrict__ C,
                          int M, int N, int K)
{
    __shared__ unsigned As[128][36];
    __shared__ unsigned Bs[128][36];

    int tid  = threadIdx.x;
    int warp = tid >> 5, lane = tid & 31;
    int wm   = warp & 1;          // 0..1 (m)
    int wn   = warp >> 1;         // 0..3 (n)
    int g    = lane >> 2;         // 0..7
    int tg   = lane & 3;          // 0..3
    int m0   = blockIdx.y * 128;
    int n0   = blockIdx.x * 128;

    int lcol  = tid & 31;
    int lrow0 = tid >> 5;

    float acc[4][4][4] = {};      // [mtile][ntile][frag]

    for (int k0 = 0; k0 < K; k0 += 32) {
        int gk = k0 + lcol;
        bool kok = (gk < K);
        #pragma unroll
        for (int r = 0; r < 128; r += 8) {
            int row = lrow0 + r;
            int gm = m0 + row;
            float v = (kok && gm < M) ? A[(size_t)gm * K + gk] : 0.0f;
            As[row][lcol] = f2tf(v);
            int gn = n0 + row;
            float w = (kok && gn < N) ? B[(size_t)gn * K + gk] : 0.0f;
            Bs[row][lcol] = f2tf(w);
        }
        __syncthreads();

        #pragma unroll
        for (int kk = 0; kk < 32; kk += 8) {
            unsigned af[4][4], bf[4][2];
            #pragma unroll
            for (int i = 0; i < 4; i++) {
                int ar = wm * 64 + i * 16;
                af[i][0] = As[ar + g    ][kk + tg    ];
                af[i][1] = As[ar + g + 8][kk + tg    ];
                af[i][2] = As[ar + g    ][kk + tg + 4];
                af[i][3] = As[ar + g + 8][kk + tg + 4];
            }
            #pragma unroll
            for (int j = 0; j < 4; j++) {
                int br = wn * 32 + j * 8;
                bf[j][0] = Bs[br + g][kk + tg    ];
                bf[j][1] = Bs[br + g][kk + tg + 4];
            }
            #pragma unroll
            for (int i = 0; i < 4; i++)
                #pragma unroll
                for (int j = 0; j < 4; j++)
                    mma_tf32(acc[i][j], af[i][0], af[i][1], af[i][2], af[i][3],
                             bf[j][0], bf[j][1]);
        }
        __syncthreads();
    }

    // Epilogue
    #pragma unroll
    for (int i = 0; i < 4; i++) {
        int row0 = m0 + wm * 64 + i * 16 + g;
        #pragma unroll
        for (int j = 0; j < 4; j++) {
            int col0 = n0 + wn * 32 + j * 8 + tg * 2;
            #pragma unroll
            for (int h = 0; h < 2; h++) {        // h=0: rows row0, h=1: row0+8
                int row = row0 + h * 8;
                if (row >= M) continue;
                #pragma unroll
                for (int cidx = 0; cidx < 2; cidx++) {
                    int col = col0 + cidx;
                    if (col >= N) continue;
                    float v = acc[i][j][h * 2 + cidx];
                    if (bias) v += bias[col];
                    C[(size_t)row * N + col] = v;
                }
            }
        }
    }
}

// ---------------------------------------------------------------------------
// Fused LSTM step on tensor cores.
// Gates GEMM: [128(batch) x 32(reordered gate cols)] per block, K=nh.
// W is gate-interleaved: row r = j*4+g corresponds to gate g of hidden unit j.
// xp (same reordering, biases folded) added in epilogue; pointwise LSTM fused.
// Block 128x32, BK=32, 256 threads (8 warps as 4(m) x 2(n)), warp tile 32x16.
// ---------------------------------------------------------------------------
__global__ void lstm_step_mma(const float* __restrict__ h_in,   // [B, nh]
                              const float* __restrict__ c_in,   // [B, nh]
                              const float* __restrict__ W,      // [4nh, nh] reordered
                              const float* __restrict__ xp,     // [B, 4nh] reordered
                              float* __restrict__ c_out,        // [B, nh]
                              float* __restrict__ y_out,        // [B, nh]
                              int nh)
{
    __shared__ unsigned As[128][36];
    __shared__ unsigned Bs[32][36];
    __shared__ float gates[128][33];

    int tid  = threadIdx.x;
    int warp = tid >> 5, lane = tid & 31;
    int wm   = warp & 3;          // 0..3 (m)
    int wn   = warp >> 2;         // 0..1 (n)
    int g    = lane >> 2;
    int tg   = lane & 3;
    int n0   = blockIdx.x * 32;   // reordered gate-col offset
    int N4   = 4 * nh;

    int lcol  = tid & 31;
    int lrow0 = tid >> 5;

    float acc[2][2][4] = {};

    for (int k0 = 0; k0 < nh; k0 += 32) {
        int gk = k0 + lcol;
        bool kok = (gk < nh);
        // A tile: h_in 128 x 32
        #pragma unroll
        for (int r = 0; r < 128; r += 8) {
            int row = lrow0 + r;
            float v = kok ? h_in[(size_t)row * nh + gk] : 0.0f;
            As[row][lcol] = f2tf(v);
        }
        // B tile: W 32 x 32
        #pragma unroll
        for (int r = 0; r < 32; r += 8) {
            int row = lrow0 + r;
            int gn = n0 + row;
            float w = (kok && gn < N4) ? W[(size_t)gn * nh + gk] : 0.0f;
            Bs[row][lcol] = f2tf(w);
        }
        __syncthreads();

        #pragma unroll
        for (int kk = 0; kk < 32; kk += 8) {
            unsigned af[2][4], bf[2][2];
            #pragma unroll
            for (int i = 0; i < 2; i++) {
                int ar = wm * 32 + i * 16;
                af[i][0] = As[ar + g    ][kk + tg    ];
                af[i][1] = As[ar + g + 8][kk + tg    ];
                af[i][2] = As[ar + g    ][kk + tg + 4];
                af[i][3] = As[ar + g + 8][kk + tg + 4];
            }
            #pragma unroll
            for (int j = 0; j < 2; j++) {
                int br = wn * 16 + j * 8;
                bf[j][0] = Bs[br + g][kk + tg    ];
                bf[j][1] = Bs[br + g][kk + tg + 4];
            }
            #pragma unroll
            for (int i = 0; i < 2; i++)
                #pragma unroll
                for (int j = 0; j < 2; j++)
                    mma_tf32(acc[i][j], af[i][0], af[i][1], af[i][2], af[i][3],
                             bf[j][0], bf[j][1]);
        }
        __syncthreads();
    }

    // Stash gates into smem
    #pragma unroll
    for (int i = 0; i < 2; i++) {
        int row0 = wm * 32 + i * 16 + g;
        #pragma unroll
        for (int j = 0; j < 2; j++) {
            int col0 = wn * 16 + j * 8 + tg * 2;
            gates[row0    ][col0    ] = acc[i][j][0];
            gates[row0    ][col0 + 1] = acc[i][j][1];
            gates[row0 + 8][col0    ] = acc[i][j][2];
            gates[row0 + 8][col0 + 1] = acc[i][j][3];
        }
    }
    __syncthreads();

    // Pointwise LSTM: 1024 (b, j) pairs; 4 per thread
    int jq = n0 >> 2;                  // global j base for this block
    #pragma unroll
    for (int p = tid; p < 1024; p += 256) {
        int b  = p >> 3;               // 0..127
        int jl = p & 7;                // 0..7
        int j  = jq + jl;
        if (j >= nh) continue;
        const float4 xv = *reinterpret_cast<const float4*>(
            xp + (size_t)b * N4 + n0 + jl * 4);
        float gi = gates[b][jl * 4 + 0] + xv.x;
        float gf = gates[b][jl * 4 + 1] + xv.y;
        float gg = gates[b][jl * 4 + 2] + xv.z;
        float go = gates[b][jl * 4 + 3] + xv.w;
        float iv = 1.0f / (1.0f + expf(-gi));
        float fv = 1.0f / (1.0f + expf(-gf));
        float gv = tanhf(gg);
        float ov = 1.0f / (1.0f + expf(-go));
        float cv = fv * c_in[(size_t)b * nh + j] + iv * gv;
        float hv = ov * tanhf(cv);
        c_out[(size_t)b * nh + j] = cv;
        y_out[(size_t)b * nh + j] = hv;
    }
}

// ---------------------------------------------------------------------------
// Host-side layer driver
// ---------------------------------------------------------------------------
static void run_layer(const float* x_in, int in_dim, int nh,
                      const float* W_ih, const float* W_hh,
                      const float* b_ih, const float* b_hh,
                      const float* h0, const float* c0,
                      float* x_out, float* xproj, float* cbuf,
                      float* Wih_r, float* Whh_r, float* bias_r)
{
    int N4 = 4 * nh;
    // Preprocess weights: gate-interleaved row order
    reorder_rows<<<N4, 256>>>(W_ih, Wih_r, nh, in_dim);
    reorder_rows<<<N4, 256>>>(W_hh, Whh_r, nh, nh);
    combine_bias<<<(N4 + 255) / 256, 256>>>(b_ih, b_hh, bias_r, nh);

    // Input projection: xproj = x_in @ Wih_r^T + bias_r   [T*B, 4nh]
    {
        dim3 grid((N4 + 127) / 128, (TT * BB) / 128);
        gemm_tf32<<<grid, 256>>>(x_in, Wih_r, bias_r, xproj, TT * BB, N4, in_dim);
    }

    // Recurrence
    dim3 gstep((N4 + 31) / 32);
    for (int t = 0; t < TT; t++) {
        const float* h_in = (t == 0) ? h0 : x_out + (size_t)(t - 1) * BB * nh;
        const float* c_in = (t == 0) ? c0 : cbuf + (size_t)((t - 1) & 1) * BB * HH;
        float* co = cbuf + (size_t)(t & 1) * BB * HH;
        float* yo = x_out + (size_t)t * BB * nh;
        const float* xp = xproj + (size_t)t * BB * N4;
        lstm_step_mma<<<gstep, 256>>>(h_in, c_in, Whh_r, xp, co, yo, nh);
    }
}

extern "C" void kernel_launch(void* const* d_in, const int* in_sizes, int n_in,
                              void* d_out, int out_size)
{
    const int*   tokens = (const int*)  d_in[0];
    const float* h0_0   = (const float*)d_in[1];
    const float* c0_0   = (const float*)d_in[2];
    const float* h0_1   = (const float*)d_in[3];
    const float* c0_1   = (const float*)d_in[4];
    const float* h0_2   = (const float*)d_in[5];
    const float* c0_2   = (const float*)d_in[6];
    const float* embw   = (const float*)d_in[7];
    const float* W_ih0  = (const float*)d_in[8];
    const float* W_hh0  = (const float*)d_in[9];
    const float* b_ih0  = (const float*)d_in[10];
    const float* b_hh0  = (const float*)d_in[11];
    const float* W_ih1  = (const float*)d_in[12];
    const float* W_hh1  = (const float*)d_in[13];
    const float* b_ih1  = (const float*)d_in[14];
    const float* b_hh1  = (const float*)d_in[15];
    const float* W_ih2  = (const float*)d_in[16];
    const float* W_hh2  = (const float*)d_in[17];
    const float* b_ih2  = (const float*)d_in[18];
    const float* b_hh2  = (const float*)d_in[19];
    const float* dec_b  = (const float*)d_in[20];
    float* logits = (float*)d_out;

    float *emb_buf, *xproj, *x1, *x2, *x3, *cbuf, *Wih_r, *Whh_r, *bias_r;
    cudaGetSymbolAddress((void**)&emb_buf, g_emb);
    cudaGetSymbolAddress((void**)&xproj,   g_xproj);
    cudaGetSymbolAddress((void**)&x1,      g_x1);
    cudaGetSymbolAddress((void**)&x2,      g_x2);
    cudaGetSymbolAddress((void**)&x3,      g_x3);
    cudaGetSymbolAddress((void**)&cbuf,    g_c);
    cudaGetSymbolAddress((void**)&Wih_r,   g_Wih_r);
    cudaGetSymbolAddress((void**)&Whh_r,   g_Whh_r);
    cudaGetSymbolAddress((void**)&bias_r,  g_bias_r);

    // 1) Embedding
    embed_kernel<<<TT * BB, 128>>>(tokens, embw, emb_buf);

    // 2) Three LSTM layers
    run_layer(emb_buf, EE, HH, W_ih0, W_hh0, b_ih0, b_hh0, h0_0, c0_0,
              x1, xproj, cbuf, Wih_r, Whh_r, bias_r);
    run_layer(x1,      HH, HH, W_ih1, W_hh1, b_ih1, b_hh1, h0_1, c0_1,
              x2, xproj, cbuf, Wih_r, Whh_r, bias_r);
    run_layer(x2,      HH, EE, W_ih2, W_hh2, b_ih2, b_hh2, h0_2, c0_2,
              x3, xproj, cbuf, Wih_r, Whh_r, bias_r);

    // 3) Tied decoder: logits = x3 @ embw^T + dec_b
    {
        dim3 grid((VV + 127) / 128, (TT * BB) / 128);
        gemm_tf32<<<grid, 256>>>(x3, embw, dec_b, logits, TT * BB, VV, EE);
    }
}

// round 5
// speedup vs baseline: 10.4211x; 2.8659x over previous
#include <cuda_runtime.h>
#include <cuda_fp16.h>
#include <math.h>

// Problem constants
#define TT 70
#define BB 128
#define EE 400
#define HH 1150
#define VV 33278

// Padded dims (K multiples of 32, strides 16B-aligned)
#define KP_E 416     // 400 -> 416
#define KP_H 1152    // 1150 -> 1152
#define N4P_H 4608   // 4*1150=4600 -> 4608 (mult of 128)
#define N4P_E 1664   // 4*400 =1600 -> 1664

// ---------------------------------------------------------------------------
// Scratch (device globals)
// ---------------------------------------------------------------------------
__device__ __half g_x0  [TT * BB * KP_E];        // embedded input, fp16, padded
__device__ __half g_x1  [TT * BB * KP_H];
__device__ __half g_x2  [TT * BB * KP_H];
__device__ __half g_x3  [TT * BB * KP_E];
__device__ __half g_embf[VV * KP_E];             // fp16 embedding table, padded
__device__ __half g_Wih [N4P_H * KP_H];          // reordered fp16 W_ih (max)
__device__ __half g_Whh [N4P_H * KP_H];          // reordered fp16 W_hh (max)
__device__ float  g_bias[N4P_H];                 // reordered combined bias, padded
__device__ float  g_xproj[TT * BB * N4P_H];      // x-projection fp32
__device__ float  g_c   [2 * BB * HH];           // cell state ping-pong (fp32)
__device__ __half g_h0f [BB * KP_H];             // padded fp16 h0

// ---------------------------------------------------------------------------
// PTX helpers
// ---------------------------------------------------------------------------
__device__ __forceinline__ void cp16(unsigned s, const void* g) {
    asm volatile("cp.async.cg.shared.global [%0], [%1], 16;" :: "r"(s), "l"(g));
}
__device__ __forceinline__ void cp16z(unsigned s, const void* g, int sz) {
    asm volatile("cp.async.cg.shared.global [%0], [%1], 16, %2;" :: "r"(s), "l"(g), "r"(sz));
}
__device__ __forceinline__ void cp_commit() {
    asm volatile("cp.async.commit_group;");
}
__device__ __forceinline__ void mma_f16(float c[4], unsigned a0, unsigned a1,
                                        unsigned a2, unsigned a3,
                                        unsigned b0, unsigned b1)
{
    asm("mma.sync.aligned.m16n8k16.row.col.f32.f16.f16.f32 "
        "{%0,%1,%2,%3},{%4,%5,%6,%7},{%8,%9},{%0,%1,%2,%3};"
        : "+f"(c[0]), "+f"(c[1]), "+f"(c[2]), "+f"(c[3])
        : "r"(a0), "r"(a1), "r"(a2), "r"(a3), "r"(b0), "r"(b1));
}
__device__ __forceinline__ unsigned lds32(const __half* p) {
    return *reinterpret_cast<const unsigned*>(p);
}

// ---------------------------------------------------------------------------
// Preprocessing kernels
// ---------------------------------------------------------------------------
__global__ void zero_half(__half* p, int n4) {   // n4 = count of uint4 (8 halfs)
    uint4 z = {0, 0, 0, 0};
    for (int i = blockIdx.x * blockDim.x + threadIdx.x; i < n4; i += gridDim.x * blockDim.x)
        reinterpret_cast<uint4*>(p)[i] = z;
}

__global__ void embed_f16(const int* __restrict__ tokens,
                          const float* __restrict__ emb,
                          __half* __restrict__ out)     // [TB][KP_E]
{
    int tb = blockIdx.x;
    int tok = tokens[tb];
    const float* src = emb + (size_t)tok * EE;
    __half* dst = out + (size_t)tb * KP_E;
    for (int e = threadIdx.x; e < KP_E; e += blockDim.x)
        dst[e] = (e < EE) ? __float2half(src[e]) : __half(0.0f);
}

__global__ void conv_emb(const float* __restrict__ emb, __half* __restrict__ out)
{
    int row = blockIdx.x;
    const float* src = emb + (size_t)row * EE;
    __half* dst = out + (size_t)row * KP_E;
    for (int e = threadIdx.x; e < KP_E; e += blockDim.x)
        dst[e] = (e < EE) ? __float2half(src[e]) : __half(0.0f);
}

// Reorder rows to gate-interleaved (r = j*4+g), convert fp16, pad rows & cols
__global__ void reorder_f16(const float* __restrict__ W, __half* __restrict__ Wr,
                            int nh, int K, int Kp)
{
    int row = blockIdx.x;                // 0..N4p-1
    int j = row >> 2, g = row & 3;
    bool valid = (row < 4 * nh);
    const float* src = W + (size_t)(g * nh + j) * K;
    __half* dst = Wr + (size_t)row * Kp;
    for (int k = threadIdx.x; k < Kp; k += blockDim.x)
        dst[k] = (valid && k < K) ? __float2half(src[k]) : __half(0.0f);
}

__global__ void combine_bias(const float* __restrict__ b1, const float* __restrict__ b2,
                             float* __restrict__ br, int nh, int N4p)
{
    int r = blockIdx.x * blockDim.x + threadIdx.x;
    if (r < N4p) {
        int j = r >> 2, g = r & 3;
        br[r] = (r < 4 * nh) ? b1[g * nh + j] + b2[g * nh + j] : 0.0f;
    }
}

__global__ void conv_h0(const float* __restrict__ h0, __half* __restrict__ out,
                        int nh, int Kp)
{
    int b = blockIdx.x;
    for (int k = threadIdx.x; k < Kp; k += blockDim.x)
        out[(size_t)b * Kp + k] = (k < nh) ? __float2half(h0[(size_t)b * nh + k])
                                           : __half(0.0f);
}

// ---------------------------------------------------------------------------
// FP16 GEMM (NT): C[m,n] = sum_k A[m,k]*B[n,k] + bias[n]
// A:[M,Kp] fp16 (rows exact), B:[*,Kp] fp16 (N valid rows), C fp32 ld=ldc.
// Block 128x128, BK=32, 256 threads (8 warps 2m x 4n), warp tile 64x32.
// cp.async double-buffered. Kp multiple of 32, strides 16B-aligned.
// ---------------------------------------------------------------------------
__global__ void __launch_bounds__(256) gemm_f16(
    const __half* __restrict__ A, const __half* __restrict__ B,
    const float* __restrict__ bias, float* __restrict__ C,
    int N, int Kp, int lda, int ldb, int ldc)
{
    __shared__ alignas(16) __half As[2][128 * 40];
    __shared__ alignas(16) __half Bs[2][128 * 40];

    int tid  = threadIdx.x;
    int warp = tid >> 5, lane = tid & 31;
    int wm = warp & 1, wn = warp >> 1;
    int g  = lane >> 2, tg = lane & 3;
    int m0 = blockIdx.y * 128;
    int n0 = blockIdx.x * 128;

    unsigned sA = (unsigned)__cvta_generic_to_shared(&As[0][0]);
    unsigned sB = (unsigned)__cvta_generic_to_shared(&Bs[0][0]);

    // chunk mapping: per stage 512 16B-chunks each for A,B; 2 per thread
    int crow[2], cko[2];
    #pragma unroll
    for (int s = 0; s < 2; s++) {
        int c = tid + s * 256;
        crow[s] = c >> 2;
        cko[s]  = (c & 3) * 8;
    }

    float acc[4][4][4] = {};

    int nk = Kp >> 5;
    // prefetch tile 0
    #pragma unroll
    for (int s = 0; s < 2; s++) {
        int row = crow[s], ko = cko[s];
        cp16(sA + (row * 40 + ko) * 2, A + (size_t)(m0 + row) * lda + ko);
        int gn = n0 + row;
        int sz = (gn < N) ? 16 : 0;
        const __half* gb = B + (size_t)(gn < N ? gn : 0) * ldb + ko;
        cp16z(sB + (row * 40 + ko) * 2, gb, sz);
    }
    cp_commit();

    for (int it = 0; it < nk; it++) {
        int buf = it & 1;
        if (it + 1 < nk) {
            int kt = (it + 1) << 5;
            int off = (buf ^ 1) * 128 * 40 * 2;
            #pragma unroll
            for (int s = 0; s < 2; s++) {
                int row = crow[s], ko = cko[s];
                cp16(sA + off + (row * 40 + ko) * 2,
                     A + (size_t)(m0 + row) * lda + kt + ko);
                int gn = n0 + row;
                int sz = (gn < N) ? 16 : 0;
                const __half* gb = B + (size_t)(gn < N ? gn : 0) * ldb + kt + ko;
                cp16z(sB + off + (row * 40 + ko) * 2, gb, sz);
            }
            cp_commit();
            asm volatile("cp.async.wait_group 1;");
        } else {
            asm volatile("cp.async.wait_group 0;");
        }
        __syncthreads();

        const __half* ab = &As[buf][0];
        const __half* bb = &Bs[buf][0];
        #pragma unroll
        for (int kk = 0; kk < 32; kk += 16) {
            unsigned af[4][4], bf[4][2];
            #pragma unroll
            for (int i = 0; i < 4; i++) {
                int ar = wm * 64 + i * 16;
                const __half* p0 = ab + (ar + g) * 40 + kk + 2 * tg;
                const __half* p1 = ab + (ar + g + 8) * 40 + kk + 2 * tg;
                af[i][0] = lds32(p0);
                af[i][1] = lds32(p1);
                af[i][2] = lds32(p0 + 8);
                af[i][3] = lds32(p1 + 8);
            }
            #pragma unroll
            for (int j = 0; j < 4; j++) {
                int br = wn * 32 + j * 8;
                const __half* p = bb + (br + g) * 40 + kk + 2 * tg;
                bf[j][0] = lds32(p);
                bf[j][1] = lds32(p + 8);
            }
            #pragma unroll
            for (int i = 0; i < 4; i++)
                #pragma unroll
                for (int j = 0; j < 4; j++)
                    mma_f16(acc[i][j], af[i][0], af[i][1], af[i][2], af[i][3],
                            bf[j][0], bf[j][1]);
        }
        __syncthreads();
    }

    // Epilogue: float2 stores (cols even, N even or padded)
    #pragma unroll
    for (int i = 0; i < 4; i++) {
        int r0 = m0 + wm * 64 + i * 16 + g;
        #pragma unroll
        for (int j = 0; j < 4; j++) {
            int col = n0 + wn * 32 + j * 8 + 2 * tg;
            if (col < N) {
                float bz = bias ? bias[col] : 0.0f;
                float bz1 = bias ? bias[col + 1] : 0.0f;
                float2 v0 = {acc[i][j][0] + bz, acc[i][j][1] + bz1};
                float2 v1 = {acc[i][j][2] + bz, acc[i][j][3] + bz1};
                *reinterpret_cast<float2*>(C + (size_t)r0 * ldc + col) = v0;
                *reinterpret_cast<float2*>(C + (size_t)(r0 + 8) * ldc + col) = v1;
            }
        }
    }
}

// ---------------------------------------------------------------------------
// Fused LSTM step (fp16 MMA). Block 64(batch) x 64(gate-cols), grid (N4p/64, 2).
// W gate-interleaved padded [N4p][Kp]; xp fp32 [B][N4p]; h fp16 padded [B][Kp].
// ---------------------------------------------------------------------------
__global__ void __launch_bounds__(256) lstm_step_f16(
    const __half* __restrict__ h_in,   // [B, Kp]
    const float*  __restrict__ c_in,   // [B, nh]
    const __half* __restrict__ W,      // [N4p, Kp]
    const float*  __restrict__ xp,     // [B, N4p]
    float* __restrict__ c_out,         // [B, nh]
    __half* __restrict__ y_out,        // [B, ldy]
    int nh, int Kp, int N4p, int ldy)
{
    __shared__ alignas(16) __half As[2][64 * 40];
    __shared__ alignas(16) __half Bs[2][64 * 40];
    __shared__ float gates[64][65];

    int tid  = threadIdx.x;
    int warp = tid >> 5, lane = tid & 31;
    int wm = warp & 1, wn = warp >> 1;
    int g  = lane >> 2, tg = lane & 3;
    int n0 = blockIdx.x * 64;
    int b0 = blockIdx.y * 64;

    unsigned sA = (unsigned)__cvta_generic_to_shared(&As[0][0]);
    unsigned sB = (unsigned)__cvta_generic_to_shared(&Bs[0][0]);

    int crow = tid >> 2;
    int cko  = (tid & 3) * 8;

    float acc[2][2][4] = {};
    int nk = Kp >> 5;

    // prefetch tile 0 (1 chunk per thread per matrix)
    cp16(sA + (crow * 40 + cko) * 2, h_in + (size_t)(b0 + crow) * Kp + cko);
    cp16(sB + (crow * 40 + cko) * 2, W + (size_t)(n0 + crow) * Kp + cko);
    cp_commit();

    for (int it = 0; it < nk; it++) {
        int buf = it & 1;
        if (it + 1 < nk) {
            int kt = (it + 1) << 5;
            int off = (buf ^ 1) * 64 * 40 * 2;
            cp16(sA + off + (crow * 40 + cko) * 2,
                 h_in + (size_t)(b0 + crow) * Kp + kt + cko);
            cp16(sB + off + (crow * 40 + cko) * 2,
                 W + (size_t)(n0 + crow) * Kp + kt + cko);
            cp_commit();
            asm volatile("cp.async.wait_group 1;");
        } else {
            asm volatile("cp.async.wait_group 0;");
        }
        __syncthreads();

        const __half* ab = &As[buf][0];
        const __half* bb = &Bs[buf][0];
        #pragma unroll
        for (int kk = 0; kk < 32; kk += 16) {
            unsigned af[2][4], bf[2][2];
            #pragma unroll
            for (int i = 0; i < 2; i++) {
                int ar = wm * 32 + i * 16;
                const __half* p0 = ab + (ar + g) * 40 + kk + 2 * tg;
                const __half* p1 = ab + (ar + g + 8) * 40 + kk + 2 * tg;
                af[i][0] = lds32(p0);
                af[i][1] = lds32(p1);
                af[i][2] = lds32(p0 + 8);
                af[i][3] = lds32(p1 + 8);
            }
            #pragma unroll
            for (int j = 0; j < 2; j++) {
                int br = wn * 16 + j * 8;
                const __half* p = bb + (br + g) * 40 + kk + 2 * tg;
                bf[j][0] = lds32(p);
                bf[j][1] = lds32(p + 8);
            }
            #pragma unroll
            for (int i = 0; i < 2; i++)
                #pragma unroll
                for (int j = 0; j < 2; j++)
                    mma_f16(acc[i][j], af[i][0], af[i][1], af[i][2], af[i][3],
                            bf[j][0], bf[j][1]);
        }
        __syncthreads();
    }

    // Stash gates into smem
    #pragma unroll
    for (int i = 0; i < 2; i++) {
        int r0 = wm * 32 + i * 16 + g;
        #pragma unroll
        for (int j = 0; j < 2; j++) {
            int col = wn * 16 + j * 8 + 2 * tg;
            gates[r0][col]         = acc[i][j][0];
            gates[r0][col + 1]     = acc[i][j][1];
            gates[r0 + 8][col]     = acc[i][j][2];
            gates[r0 + 8][col + 1] = acc[i][j][3];
        }
    }
    __syncthreads();

    // Pointwise LSTM: 64 batch x 16 hidden units
    int jbase = blockIdx.x * 16;
    #pragma unroll
    for (int p = tid; p < 1024; p += 256) {
        int b  = p >> 4;              // 0..63
        int jl = p & 15;              // 0..15
        int j  = jbase + jl;
        if (j >= nh) continue;
        int bg = b0 + b;
        const float4 xv = *reinterpret_cast<const float4*>(
            xp + (size_t)bg * N4p + n0 + jl * 4);
        float gi = gates[b][jl * 4 + 0] + xv.x;
        float gf = gates[b][jl * 4 + 1] + xv.y;
        float gg = gates[b][jl * 4 + 2] + xv.z;
        float go = gates[b][jl * 4 + 3] + xv.w;
        float iv = 1.0f / (1.0f + expf(-gi));
        float fv = 1.0f / (1.0f + expf(-gf));
        float gv = tanhf(gg);
        float ov = 1.0f / (1.0f + expf(-go));
        float cv = fv * c_in[(size_t)bg * nh + j] + iv * gv;
        float hv = ov * tanhf(cv);
        c_out[(size_t)bg * nh + j] = cv;
        y_out[(size_t)bg * ldy + j] = __float2half(hv);
    }
}

// ---------------------------------------------------------------------------
// Layer driver
// ---------------------------------------------------------------------------
static void run_layer(const __half* x_in, int Kp_in, int nh, int Kp_h, int N4p,
                      const float* W_ih, const float* W_hh,
                      const float* b_ih, const float* b_hh,
                      const float* h0, const float* c0,
                      __half* x_out, int ld_out,
                      __half* Wih, __half* Whh, float* bias,
                      float* xproj, float* cbuf, __half* h0f)
{
    reorder_f16<<<N4p, 256>>>(W_ih, Wih, nh, (Kp_in == KP_E) ? EE : HH, Kp_in);
    reorder_f16<<<N4p, 256>>>(W_hh, Whh, nh, nh, Kp_h);
    combine_bias<<<(N4p + 255) / 256, 256>>>(b_ih, b_hh, bias, nh, N4p);
    conv_h0<<<BB, 256>>>(h0, h0f, nh, Kp_h);

    // Input projection: xproj = x_in @ Wih^T + bias   [T*B, N4p]
    {
        dim3 grid(N4p / 128, (TT * BB) / 128);
        gemm_f16<<<grid, 256>>>(x_in, Wih, bias, xproj, N4p, Kp_in,
                                Kp_in, Kp_in, N4p);
    }

    // Recurrence
    dim3 gstep(N4p / 64, 2);
    for (int t = 0; t < TT; t++) {
        const __half* h_in = (t == 0) ? h0f : x_out + (size_t)(t - 1) * BB * ld_out;
        const float*  c_in = (t == 0) ? c0  : cbuf + (size_t)((t - 1) & 1) * BB * HH;
        float* co = cbuf + (size_t)(t & 1) * BB * HH;
        __half* yo = x_out + (size_t)t * BB * ld_out;
        const float* xpt = xproj + (size_t)t * BB * N4p;
        lstm_step_f16<<<gstep, 256>>>(h_in, c_in, Whh, xpt, co, yo,
                                      nh, Kp_h, N4p, ld_out);
    }
}

extern "C" void kernel_launch(void* const* d_in, const int* in_sizes, int n_in,
                              void* d_out, int out_size)
{
    const int*   tokens = (const int*)  d_in[0];
    const float* h0_0   = (const float*)d_in[1];
    const float* c0_0   = (const float*)d_in[2];
    const float* h0_1   = (const float*)d_in[3];
    const float* c0_1   = (const float*)d_in[4];
    const float* h0_2   = (const float*)d_in[5];
    const float* c0_2   = (const float*)d_in[6];
    const float* embw   = (const float*)d_in[7];
    const float* W_ih0  = (const float*)d_in[8];
    const float* W_hh0  = (const float*)d_in[9];
    const float* b_ih0  = (const float*)d_in[10];
    const float* b_hh0  = (const float*)d_in[11];
    const float* W_ih1  = (const float*)d_in[12];
    const float* W_hh1  = (const float*)d_in[13];
    const float* b_ih1  = (const float*)d_in[14];
    const float* b_hh1  = (const float*)d_in[15];
    const float* W_ih2  = (const float*)d_in[16];
    const float* W_hh2  = (const float*)d_in[17];
    const float* b_ih2  = (const float*)d_in[18];
    const float* b_hh2  = (const float*)d_in[19];
    const float* dec_b  = (const float*)d_in[20];
    float* logits = (float*)d_out;

    __half *x0, *x1, *x2, *x3, *embf, *Wih, *Whh, *h0f;
    float *bias, *xproj, *cbuf;
    cudaGetSymbolAddress((void**)&x0,    g_x0);
    cudaGetSymbolAddress((void**)&x1,    g_x1);
    cudaGetSymbolAddress((void**)&x2,    g_x2);
    cudaGetSymbolAddress((void**)&x3,    g_x3);
    cudaGetSymbolAddress((void**)&embf,  g_embf);
    cudaGetSymbolAddress((void**)&Wih,   g_Wih);
    cudaGetSymbolAddress((void**)&Whh,   g_Whh);
    cudaGetSymbolAddress((void**)&bias,  g_bias);
    cudaGetSymbolAddress((void**)&xproj, g_xproj);
    cudaGetSymbolAddress((void**)&cbuf,  g_c);
    cudaGetSymbolAddress((void**)&h0f,   g_h0f);

    // Zero pad columns of activation buffers (whole-buffer zero, cheap)
    zero_half<<<512, 256>>>(x1, TT * BB * KP_H / 8);
    zero_half<<<512, 256>>>(x2, TT * BB * KP_H / 8);
    zero_half<<<512, 256>>>(x3, TT * BB * KP_E / 8);

    // Preprocess: embedding gather + fp16 embedding table
    embed_f16<<<TT * BB, 256>>>(tokens, embw, x0);
    conv_emb<<<VV, 128>>>(embw, embf);

    // Three LSTM layers
    run_layer(x0, KP_E, HH, KP_H, N4P_H, W_ih0, W_hh0, b_ih0, b_hh0, h0_0, c0_0,
              x1, KP_H, Wih, Whh, bias, xproj, cbuf, h0f);
    run_layer(x1, KP_H, HH, KP_H, N4P_H, W_ih1, W_hh1, b_ih1, b_hh1, h0_1, c0_1,
              x2, KP_H, Wih, Whh, bias, xproj, cbuf, h0f);
    run_layer(x2, KP_H, EE, KP_E, N4P_E, W_ih2, W_hh2, b_ih2, b_hh2, h0_2, c0_2,
              x3, KP_E, Wih, Whh, bias, xproj, cbuf, h0f);

    // Tied decoder: logits = x3 @ embf^T + dec_b   [T*B, V]
    {
        dim3 grid((VV + 127) / 128, (TT * BB) / 128);
        gemm_f16<<<grid, 256>>>(x3, embf, dec_b, logits, VV, KP_E,
                                KP_E, KP_E, VV);
    }
}